// round 14
// baseline (speedup 1.0000x reference)
#include <cuda_runtime.h>

#define NN 50000
#define EE 800000
#define DD 96
#define NV4 (NN * DD / 4)
#define NBLK ((NN + 255) / 256)        // 196 scan blocks

// ---------------- scratch (device globals; no allocation allowed) ----------
__device__ __align__(256) float g_deg[NN];      // out-degree (by row)
__device__ __align__(256) int   g_cnt[NN];      // in-degree (by col)
__device__ __align__(256) int   g_ptr[NN + 1];  // CSR row pointers (by dst)
__device__ __align__(256) int   g_fill[NN];     // atomic cursors
__device__ __align__(256) int   g_bsum[256];    // scan block sums
__device__ __align__(256) int   g_boff[256];    // scan block offsets
__device__ __align__(256) int2  g_cedge[EE];    // {src_row, norm bits}
__device__ __align__(256) float g_T1[NN * DD];
__device__ __align__(256) float g_P[NN * DD];
__device__ __align__(256) float g_acc[NN * DD];
__device__ __align__(256) float g_colsum[DD];
__device__ __align__(256) float g_colsumsq[DD];

// ---------------- packed f32x2 FMA (SASS FFMA2) -----------------------------
__device__ __forceinline__ void ffma2(unsigned long long& d,
                                      unsigned long long a,
                                      unsigned long long b) {
    asm("fma.rn.f32x2 %0, %1, %2, %0;" : "+l"(d) : "l"(a), "l"(b));
}

// ---------------- zero small scratch ----------------------------------------
__global__ void zero_kernel() {
    int tid = blockIdx.x * blockDim.x + threadIdx.x;
    int stride = gridDim.x * blockDim.x;
    for (int i = tid; i < NN; i += stride) { g_deg[i] = 0.f; g_cnt[i] = 0; }
    if (tid < DD) { g_colsum[tid] = 0.f; g_colsumsq[tid] = 0.f; }
}

// ---------------- histogram: 4 edges/thread via int4 loads ------------------
__global__ void hist_kernel(const int* __restrict__ ei) {
    int e4 = (blockIdx.x * blockDim.x + threadIdx.x) * 4;
    if (e4 >= EE) return;
    int4 rr = *reinterpret_cast<const int4*>(ei + e4);
    int4 cc = *reinterpret_cast<const int4*>(ei + EE + e4);
    if (rr.x != cc.x) { atomicAdd(&g_deg[rr.x], 1.0f); atomicAdd(&g_cnt[cc.x], 1); }
    if (rr.y != cc.y) { atomicAdd(&g_deg[rr.y], 1.0f); atomicAdd(&g_cnt[cc.y], 1); }
    if (rr.z != cc.z) { atomicAdd(&g_deg[rr.z], 1.0f); atomicAdd(&g_cnt[cc.z], 1); }
    if (rr.w != cc.w) { atomicAdd(&g_deg[rr.w], 1.0f); atomicAdd(&g_cnt[cc.w], 1); }
}

// ---------------- multi-block exclusive scan of g_cnt -> g_ptr --------------
__global__ void scan1_kernel() {                 // per-block scan + block sums
    __shared__ int sh[256];
    int i = blockIdx.x * 256 + threadIdx.x;
    int v = (i < NN) ? g_cnt[i] : 0;
    sh[threadIdx.x] = v;
    __syncthreads();
#pragma unroll
    for (int off = 1; off < 256; off <<= 1) {
        int t = (threadIdx.x >= off) ? sh[threadIdx.x - off] : 0;
        __syncthreads();
        sh[threadIdx.x] += t;
        __syncthreads();
    }
    if (i < NN) g_ptr[i] = sh[threadIdx.x] - v;  // block-local exclusive
    if (threadIdx.x == 255) g_bsum[blockIdx.x] = sh[255];
}

__global__ void scan2_kernel() {                 // scan the 196 block sums
    __shared__ int sh[256];
    int b = threadIdx.x;
    int v = (b < NBLK) ? g_bsum[b] : 0;
    sh[b] = v;
    __syncthreads();
#pragma unroll
    for (int off = 1; off < 256; off <<= 1) {
        int t = (b >= off) ? sh[b - off] : 0;
        __syncthreads();
        sh[b] += t;
        __syncthreads();
    }
    if (b < NBLK) g_boff[b] = sh[b] - v;
    if (b == 255) g_ptr[NN] = sh[255];           // total kept edges
}

__global__ void scan3_kernel() {                 // add offsets, init cursors
    int i = blockIdx.x * 256 + threadIdx.x;
    if (i >= NN) return;
    int p = g_ptr[i] + g_boff[blockIdx.x];
    g_ptr[i] = p;
    g_fill[i] = p;
}

// ---------------- scatter: 4 edges/thread, independent chains ---------------
__global__ void scatter_kernel(const int* __restrict__ ei) {
    int e4 = (blockIdx.x * blockDim.x + threadIdx.x) * 4;
    if (e4 >= EE) return;
    int4 rr = *reinterpret_cast<const int4*>(ei + e4);
    int4 cc = *reinterpret_cast<const int4*>(ei + EE + e4);
    int r[4] = {rr.x, rr.y, rr.z, rr.w};
    int c[4] = {cc.x, cc.y, cc.z, cc.w};

    float dr[4], dc[4];
#pragma unroll
    for (int i = 0; i < 4; i++) {
        dr[i] = g_deg[r[i]];
        dc[i] = g_deg[c[i]];
    }
#pragma unroll
    for (int i = 0; i < 4; i++) {
        if (r[i] == c[i]) continue;
        float ir = (dr[i] > 0.f) ? rsqrtf(fmaxf(dr[i], 1e-12f)) : 0.f;
        float ic = (dc[i] > 0.f) ? rsqrtf(fmaxf(dc[i], 1e-12f)) : 0.f;
        float nrm = -ir * ic;
        int pos = atomicAdd(&g_fill[c[i]], 1);
        g_cedge[pos] = make_int2(r[i], __float_as_int(nrm));
    }
}

// ---------------- pull-mode SpMM: 4-edge unroll, int4 edge loads ------------
// One warp per destination node; lane covers features {lane, +32, +64}.
__global__ void spmm_pull_kernel(int pass, const float* __restrict__ x) {
    const float* src = (pass == 0) ? x : g_T1;
    float* dst = (pass == 0) ? g_T1 : g_P;

    int node = (blockIdx.x * blockDim.x + threadIdx.x) >> 5;
    if (node >= NN) return;
    int lane = threadIdx.x & 31;

    int beg = g_ptr[node], end = g_ptr[node + 1];
    float a0 = 0.f, a1 = 0.f, a2 = 0.f;

    int e = beg;
    // 4-edge unrolled main loop; edge records loaded as 2 x int4 when aligned
    for (; e + 3 < end; e += 4) {
        int2 e0, e1, e2, e3;
        if ((e & 1) == 0) {                 // 16B-aligned pair loads
            int4 q0 = *reinterpret_cast<const int4*>(&g_cedge[e]);
            int4 q1 = *reinterpret_cast<const int4*>(&g_cedge[e + 2]);
            e0 = make_int2(q0.x, q0.y); e1 = make_int2(q0.z, q0.w);
            e2 = make_int2(q1.x, q1.y); e3 = make_int2(q1.z, q1.w);
        } else {
            e0 = __ldg(&g_cedge[e]);     e1 = __ldg(&g_cedge[e + 1]);
            e2 = __ldg(&g_cedge[e + 2]); e3 = __ldg(&g_cedge[e + 3]);
        }
        float n0 = __int_as_float(e0.y), n1 = __int_as_float(e1.y);
        float n2 = __int_as_float(e2.y), n3 = __int_as_float(e3.y);
        const float* s0 = src + e0.x * DD;
        const float* s1 = src + e1.x * DD;
        const float* s2 = src + e2.x * DD;
        const float* s3 = src + e3.x * DD;
        // issue all 12 loads before consuming — max MLP
        float v00 = __ldg(s0 + lane), v01 = __ldg(s0 + lane + 32), v02 = __ldg(s0 + lane + 64);
        float v10 = __ldg(s1 + lane), v11 = __ldg(s1 + lane + 32), v12 = __ldg(s1 + lane + 64);
        float v20 = __ldg(s2 + lane), v21 = __ldg(s2 + lane + 32), v22 = __ldg(s2 + lane + 64);
        float v30 = __ldg(s3 + lane), v31 = __ldg(s3 + lane + 32), v32 = __ldg(s3 + lane + 64);
        a0 += n0 * v00 + n1 * v10 + n2 * v20 + n3 * v30;
        a1 += n0 * v01 + n1 * v11 + n2 * v21 + n3 * v31;
        a2 += n0 * v02 + n1 * v12 + n2 * v22 + n3 * v32;
    }
    for (; e < end; e++) {
        int2 e0 = __ldg(&g_cedge[e]);
        float n0 = __int_as_float(e0.y);
        const float* s0 = src + e0.x * DD;
        a0 += n0 * __ldg(s0 + lane);
        a1 += n0 * __ldg(s0 + lane + 32);
        a2 += n0 * __ldg(s0 + lane + 64);
    }

    float* d = dst + node * DD;
    d[lane] = a0;
    d[lane + 32] = a1;
    d[lane + 64] = a2;
}

// ---------------- persistent GEMM + bias + column stats (round-12 verbatim) -
#define GEMM_THREADS 384
#define RPB 64
#define NSM 148
#define WS_STRIDE 100
#define WS_MAT (DD * WS_STRIDE)
#define GBLK ((NN + RPB - 1) / RPB)
#define ROW4 (DD / 4)
#define TILE4 (RPB * ROW4)
#define PFQ (TILE4 / GEMM_THREADS)
#define SMEM_FLOATS (3 * WS_MAT + DD + 3 * RPB * DD + 2 * DD)
#define SMEM_BYTES (SMEM_FLOATS * 4)

__global__ __launch_bounds__(GEMM_THREADS, 1)
void gemm_kernel(const float* __restrict__ x, const float* __restrict__ W,
                 const float* __restrict__ bias) {
    extern __shared__ float smem[];
    float* Ws   = smem;
    float* bs   = Ws + 3 * WS_MAT;
    float* xs   = bs + DD;
    float* t1s  = xs + RPB * DD;
    float* t2s  = t1s + RPB * DD;
    float* stat = t2s + RPB * DD;

    int tid = threadIdx.x;

    for (int i = tid; i < 3 * DD * DD; i += GEMM_THREADS) {
        int kk = i / (DD * DD);
        int rem = i - kk * DD * DD;
        int k = rem / DD;
        int j = rem - k * DD;
        Ws[kk * WS_MAT + j * WS_STRIDE + k] = W[i];
    }
    if (tid < DD) bs[tid] = bias[tid];
    if (tid < 2 * DD) stat[tid] = 0.f;

    const float4* x4  = reinterpret_cast<const float4*>(x);
    const float4* t14 = reinterpret_cast<const float4*>(g_T1);
    const float4* p4  = reinterpret_cast<const float4*>(g_P);
    float4* xs4  = reinterpret_cast<float4*>(xs);
    float4* t1s4 = reinterpret_cast<float4*>(t1s);
    float4* t2s4 = reinterpret_cast<float4*>(t2s);

    int tx = tid % 24;
    int ty = tid / 24;

    float4 pf[3 * PFQ];
    int tile = blockIdx.x;
    {
#pragma unroll
        for (int q = 0; q < PFQ; q++) {
            int idx = tid + q * GEMM_THREADS;
            int row = tile * RPB + idx / ROW4;
            float4 xv = make_float4(0.f, 0.f, 0.f, 0.f), t1v = xv, t2v = xv;
            if (row < NN) {
                int gi = row * ROW4 + (idx % ROW4);
                xv = __ldg(x4 + gi);
                t1v = t14[gi];
                float4 pv = p4[gi];
                t2v = make_float4(2.f * pv.x - xv.x, 2.f * pv.y - xv.y,
                                  2.f * pv.z - xv.z, 2.f * pv.w - xv.w);
            }
            pf[q * 3 + 0] = xv; pf[q * 3 + 1] = t1v; pf[q * 3 + 2] = t2v;
        }
    }
    __syncthreads();
#pragma unroll
    for (int q = 0; q < PFQ; q++) {
        int idx = tid + q * GEMM_THREADS;
        xs4[idx] = pf[q * 3 + 0]; t1s4[idx] = pf[q * 3 + 1]; t2s4[idx] = pf[q * 3 + 2];
    }
    __syncthreads();

    float cs[4] = {0.f, 0.f, 0.f, 0.f};
    float cs2[4] = {0.f, 0.f, 0.f, 0.f};

    for (;;) {
        int next = tile + NSM;
        bool has_next = (next < GBLK);

        if (has_next) {
#pragma unroll
            for (int q = 0; q < PFQ; q++) {
                int idx = tid + q * GEMM_THREADS;
                int row = next * RPB + idx / ROW4;
                float4 xv = make_float4(0.f, 0.f, 0.f, 0.f), t1v = xv, t2v = xv;
                if (row < NN) {
                    int gi = row * ROW4 + (idx % ROW4);
                    xv = __ldg(x4 + gi);
                    t1v = t14[gi];
                    float4 pv = p4[gi];
                    t2v = make_float4(2.f * pv.x - xv.x, 2.f * pv.y - xv.y,
                                      2.f * pv.z - xv.z, 2.f * pv.w - xv.w);
                }
                pf[q * 3 + 0] = xv; pf[q * 3 + 1] = t1v; pf[q * 3 + 2] = t2v;
            }
        }

        unsigned long long acc[4][4];
#pragma unroll
        for (int r = 0; r < 4; r++)
#pragma unroll
            for (int jj = 0; jj < 4; jj++) acc[r][jj] = 0ULL;

        const float* xrow  = xs  + ty * 4 * DD;
        const float* t1row = t1s + ty * 4 * DD;
        const float* t2row = t2s + ty * 4 * DD;

        for (int k = 0; k < DD; k += 4) {
            ulonglong2 w0[4], w1[4], w2[4];
#pragma unroll
            for (int jj = 0; jj < 4; jj++) {
                int j = tx + jj * 24;
                w0[jj] = *reinterpret_cast<const ulonglong2*>(&Ws[0 * WS_MAT + j * WS_STRIDE + k]);
                w1[jj] = *reinterpret_cast<const ulonglong2*>(&Ws[1 * WS_MAT + j * WS_STRIDE + k]);
                w2[jj] = *reinterpret_cast<const ulonglong2*>(&Ws[2 * WS_MAT + j * WS_STRIDE + k]);
            }
#pragma unroll
            for (int r = 0; r < 4; r++) {
                ulonglong2 xv = *reinterpret_cast<const ulonglong2*>(&xrow[r * DD + k]);
                ulonglong2 av = *reinterpret_cast<const ulonglong2*>(&t1row[r * DD + k]);
                ulonglong2 bv = *reinterpret_cast<const ulonglong2*>(&t2row[r * DD + k]);
#pragma unroll
                for (int jj = 0; jj < 4; jj++) {
                    ffma2(acc[r][jj], xv.x, w0[jj].x);
                    ffma2(acc[r][jj], xv.y, w0[jj].y);
                    ffma2(acc[r][jj], av.x, w1[jj].x);
                    ffma2(acc[r][jj], av.y, w1[jj].y);
                    ffma2(acc[r][jj], bv.x, w2[jj].x);
                    ffma2(acc[r][jj], bv.y, w2[jj].y);
                }
            }
        }

        int base = tile * RPB;
#pragma unroll
        for (int jj = 0; jj < 4; jj++) {
            int j = tx + jj * 24;
            float bj = bs[j];
#pragma unroll
            for (int r = 0; r < 4; r++) {
                int row = base + ty * 4 + r;
                if (row < NN) {
                    unsigned int lo_b, hi_b;
                    asm("mov.b64 {%0, %1}, %2;" : "=r"(lo_b), "=r"(hi_b) : "l"(acc[r][jj]));
                    float v = __uint_as_float(lo_b) + __uint_as_float(hi_b) + bj;
                    g_acc[row * DD + j] = v;
                    cs[jj] += v; cs2[jj] += v * v;
                }
            }
        }

        if (!has_next) break;
        __syncthreads();
#pragma unroll
        for (int q = 0; q < PFQ; q++) {
            int idx = tid + q * GEMM_THREADS;
            xs4[idx] = pf[q * 3 + 0]; t1s4[idx] = pf[q * 3 + 1]; t2s4[idx] = pf[q * 3 + 2];
        }
        __syncthreads();
        tile = next;
    }

    __syncthreads();
#pragma unroll
    for (int jj = 0; jj < 4; jj++) {
        int j = tx + jj * 24;
        atomicAdd(&stat[j], cs[jj]);
        atomicAdd(&stat[DD + j], cs2[jj]);
    }
    __syncthreads();
    if (tid < DD) {
        atomicAdd(&g_colsum[tid], stat[tid]);
        atomicAdd(&g_colsumsq[tid], stat[DD + tid]);
    }
}

// ---------------- BatchNorm: stats finalize fused into apply ----------------
__global__ void bn_apply_kernel(const float* __restrict__ gamma,
                                const float* __restrict__ beta,
                                float* __restrict__ out) {
    __shared__ float sc[DD], sh[DD];
    if (threadIdx.x < DD) {
        int j = threadIdx.x;
        float inv_n = 1.0f / (float)NN;
        float mean = g_colsum[j] * inv_n;
        float var = fmaxf(g_colsumsq[j] * inv_n - mean * mean, 0.f);
        float istd = rsqrtf(var + 1e-5f);
        float s = gamma[j] * istd;
        sc[j] = s;
        sh[j] = beta[j] - mean * s;
    }
    __syncthreads();
    int tid = blockIdx.x * blockDim.x + threadIdx.x;
    int stride = gridDim.x * blockDim.x;
    const float4* in4 = reinterpret_cast<const float4*>(g_acc);
    float4* o4 = reinterpret_cast<float4*>(out);
    for (int i = tid; i < NV4; i += stride) {
        int c4 = i % (DD / 4);
        int j = c4 * 4;
        float4 v = in4[i];
        o4[i] = make_float4(v.x * sc[j]     + sh[j],
                            v.y * sc[j + 1] + sh[j + 1],
                            v.z * sc[j + 2] + sh[j + 2],
                            v.w * sc[j + 3] + sh[j + 3]);
    }
}

// ---------------- launch ----------------------------------------------------
extern "C" void kernel_launch(void* const* d_in, const int* in_sizes, int n_in,
                              void* d_out, int out_size) {
    const float* x     = (const float*)d_in[0];
    const int*   ei    = (const int*)d_in[1];
    const float* W     = (const float*)d_in[2];
    const float* bias  = (const float*)d_in[3];
    const float* gamma = (const float*)d_in[4];
    const float* beta  = (const float*)d_in[5];
    float* out = (float*)d_out;

    cudaFuncSetAttribute(gemm_kernel,
                         cudaFuncAttributeMaxDynamicSharedMemorySize, SMEM_BYTES);

    zero_kernel<<<256, 256>>>();
    hist_kernel<<<(EE / 4 + 255) / 256, 256>>>(ei);
    scan1_kernel<<<NBLK, 256>>>();
    scan2_kernel<<<1, 256>>>();
    scan3_kernel<<<NBLK, 256>>>();
    scatter_kernel<<<(EE / 4 + 255) / 256, 256>>>(ei);
    // prop 1: T1 = L_hat @ x  (pull, no atomics, no zero-init)
    spmm_pull_kernel<<<(NN * 32 + 255) / 256, 256>>>(0, x);
    // prop 2: P = L_hat @ T1
    spmm_pull_kernel<<<(NN * 32 + 255) / 256, 256>>>(1, x);
    gemm_kernel<<<NSM, GEMM_THREADS, SMEM_BYTES>>>(x, W, bias);
    bn_apply_kernel<<<2048, 256>>>(gamma, beta, out);
}

// round 15
// speedup vs baseline: 1.0105x; 1.0105x over previous
#include <cuda_runtime.h>

#define NN 50000
#define EE 800000
#define DD 96
#define NV4 (NN * DD / 4)
#define NBLK ((NN + 255) / 256)        // 196 scan blocks

// ---------------- scratch (device globals; no allocation allowed) ----------
__device__ __align__(256) float g_deg[NN];      // out-degree (by row)
__device__ __align__(256) int   g_cnt[NN];      // in-degree (by col)
__device__ __align__(256) int   g_ptr[NN + 1];  // CSR row pointers (by dst)
__device__ __align__(256) int   g_fill[NN];     // atomic cursors
__device__ __align__(256) int   g_bsum[256];    // scan block sums
__device__ __align__(256) int2  g_cedge[EE];    // {src_row, norm bits}
__device__ __align__(256) float g_T1[NN * DD];
__device__ __align__(256) float g_P[NN * DD];
__device__ __align__(256) float g_acc[NN * DD];
__device__ __align__(256) float g_colsum[DD];
__device__ __align__(256) float g_colsumsq[DD];

// ---------------- packed f32x2 FMA (SASS FFMA2) -----------------------------
__device__ __forceinline__ void ffma2(unsigned long long& d,
                                      unsigned long long a,
                                      unsigned long long b) {
    asm("fma.rn.f32x2 %0, %1, %2, %0;" : "+l"(d) : "l"(a), "l"(b));
}

// ---------------- zero small scratch ----------------------------------------
__global__ void zero_kernel() {
    int tid = blockIdx.x * blockDim.x + threadIdx.x;
    int stride = gridDim.x * blockDim.x;
    for (int i = tid; i < NN; i += stride) { g_deg[i] = 0.f; g_cnt[i] = 0; }
    if (tid < DD) { g_colsum[tid] = 0.f; g_colsumsq[tid] = 0.f; }
}

// ---------------- histogram: 4 edges/thread via int4 loads ------------------
__global__ void hist_kernel(const int* __restrict__ ei) {
    int e4 = (blockIdx.x * blockDim.x + threadIdx.x) * 4;
    if (e4 >= EE) return;
    int4 rr = *reinterpret_cast<const int4*>(ei + e4);
    int4 cc = *reinterpret_cast<const int4*>(ei + EE + e4);
    if (rr.x != cc.x) { atomicAdd(&g_deg[rr.x], 1.0f); atomicAdd(&g_cnt[cc.x], 1); }
    if (rr.y != cc.y) { atomicAdd(&g_deg[rr.y], 1.0f); atomicAdd(&g_cnt[cc.y], 1); }
    if (rr.z != cc.z) { atomicAdd(&g_deg[rr.z], 1.0f); atomicAdd(&g_cnt[cc.z], 1); }
    if (rr.w != cc.w) { atomicAdd(&g_deg[rr.w], 1.0f); atomicAdd(&g_cnt[cc.w], 1); }
}

// ---------------- scan stage 1: per-block scan + block sums -----------------
__global__ void scan1_kernel() {
    __shared__ int sh[256];
    int i = blockIdx.x * 256 + threadIdx.x;
    int v = (i < NN) ? g_cnt[i] : 0;
    sh[threadIdx.x] = v;
    __syncthreads();
#pragma unroll
    for (int off = 1; off < 256; off <<= 1) {
        int t = (threadIdx.x >= off) ? sh[threadIdx.x - off] : 0;
        __syncthreads();
        sh[threadIdx.x] += t;
        __syncthreads();
    }
    if (i < NN) g_ptr[i] = sh[threadIdx.x] - v;  // block-local exclusive
    if (threadIdx.x == 255) g_bsum[blockIdx.x] = sh[255];
}

// ---------------- scan stage 2: each block redundantly scans block sums -----
// (merges old scan2+scan3 — one launch instead of two)
__global__ void scan2_kernel() {
    __shared__ int sh[256];
    __shared__ int myoff;
    int b = threadIdx.x;
    int v = (b < NBLK) ? g_bsum[b] : 0;
    sh[b] = v;
    __syncthreads();
#pragma unroll
    for (int off = 1; off < 256; off <<= 1) {
        int t = (b >= off) ? sh[b - off] : 0;
        __syncthreads();
        sh[b] += t;
        __syncthreads();
    }
    if (threadIdx.x == blockIdx.x) myoff = sh[threadIdx.x] - v;   // exclusive offset
    __syncthreads();
    int i = blockIdx.x * 256 + threadIdx.x;
    if (i < NN) {
        int p = g_ptr[i] + myoff;
        g_ptr[i] = p;
        g_fill[i] = p;
    }
    if (blockIdx.x == NBLK - 1 && threadIdx.x == 255)
        g_ptr[NN] = sh[NBLK - 1];                 // total kept edges
}

// ---------------- scatter: 4 edges/thread, independent chains ---------------
__global__ void scatter_kernel(const int* __restrict__ ei) {
    int e4 = (blockIdx.x * blockDim.x + threadIdx.x) * 4;
    if (e4 >= EE) return;
    int4 rr = *reinterpret_cast<const int4*>(ei + e4);
    int4 cc = *reinterpret_cast<const int4*>(ei + EE + e4);
    int r[4] = {rr.x, rr.y, rr.z, rr.w};
    int c[4] = {cc.x, cc.y, cc.z, cc.w};

    float dr[4], dc[4];
#pragma unroll
    for (int i = 0; i < 4; i++) {
        dr[i] = g_deg[r[i]];
        dc[i] = g_deg[c[i]];
    }
#pragma unroll
    for (int i = 0; i < 4; i++) {
        if (r[i] == c[i]) continue;
        float ir = (dr[i] > 0.f) ? rsqrtf(fmaxf(dr[i], 1e-12f)) : 0.f;
        float ic = (dc[i] > 0.f) ? rsqrtf(fmaxf(dc[i], 1e-12f)) : 0.f;
        float nrm = -ir * ic;
        int pos = atomicAdd(&g_fill[c[i]], 1);
        g_cedge[pos] = make_int2(r[i], __float_as_int(nrm));
    }
}

// ---------------- pull-mode SpMM (round-13 verbatim) ------------------------
// One warp per destination node; lane covers features {lane, +32, +64}.
__global__ void spmm_pull_kernel(int pass, const float* __restrict__ x) {
    const float* src = (pass == 0) ? x : g_T1;
    float* dst = (pass == 0) ? g_T1 : g_P;

    int node = (blockIdx.x * blockDim.x + threadIdx.x) >> 5;
    if (node >= NN) return;
    int lane = threadIdx.x & 31;

    int beg = g_ptr[node], end = g_ptr[node + 1];
    float a0 = 0.f, a1 = 0.f, a2 = 0.f;

    int e = beg;
    for (; e + 1 < end; e += 2) {
        int2 e0 = __ldg(&g_cedge[e]);
        int2 e1 = __ldg(&g_cedge[e + 1]);
        float n0 = __int_as_float(e0.y);
        float n1 = __int_as_float(e1.y);
        const float* s0 = src + e0.x * DD;
        const float* s1 = src + e1.x * DD;
        float v00 = __ldg(s0 + lane), v01 = __ldg(s0 + lane + 32), v02 = __ldg(s0 + lane + 64);
        float v10 = __ldg(s1 + lane), v11 = __ldg(s1 + lane + 32), v12 = __ldg(s1 + lane + 64);
        a0 += n0 * v00 + n1 * v10;
        a1 += n0 * v01 + n1 * v11;
        a2 += n0 * v02 + n1 * v12;
    }
    if (e < end) {
        int2 e0 = __ldg(&g_cedge[e]);
        float n0 = __int_as_float(e0.y);
        const float* s0 = src + e0.x * DD;
        a0 += n0 * __ldg(s0 + lane);
        a1 += n0 * __ldg(s0 + lane + 32);
        a2 += n0 * __ldg(s0 + lane + 64);
    }

    float* d = dst + node * DD;
    d[lane] = a0;
    d[lane + 32] = a1;
    d[lane + 64] = a2;
}

// ---------------- persistent GEMM + bias + column stats (round-12 verbatim) -
#define GEMM_THREADS 384
#define RPB 64
#define NSM 148
#define WS_STRIDE 100
#define WS_MAT (DD * WS_STRIDE)
#define GBLK ((NN + RPB - 1) / RPB)
#define ROW4 (DD / 4)
#define TILE4 (RPB * ROW4)
#define PFQ (TILE4 / GEMM_THREADS)
#define SMEM_FLOATS (3 * WS_MAT + DD + 3 * RPB * DD + 2 * DD)
#define SMEM_BYTES (SMEM_FLOATS * 4)

__global__ __launch_bounds__(GEMM_THREADS, 1)
void gemm_kernel(const float* __restrict__ x, const float* __restrict__ W,
                 const float* __restrict__ bias) {
    extern __shared__ float smem[];
    float* Ws   = smem;
    float* bs   = Ws + 3 * WS_MAT;
    float* xs   = bs + DD;
    float* t1s  = xs + RPB * DD;
    float* t2s  = t1s + RPB * DD;
    float* stat = t2s + RPB * DD;

    int tid = threadIdx.x;

    for (int i = tid; i < 3 * DD * DD; i += GEMM_THREADS) {
        int kk = i / (DD * DD);
        int rem = i - kk * DD * DD;
        int k = rem / DD;
        int j = rem - k * DD;
        Ws[kk * WS_MAT + j * WS_STRIDE + k] = W[i];
    }
    if (tid < DD) bs[tid] = bias[tid];
    if (tid < 2 * DD) stat[tid] = 0.f;

    const float4* x4  = reinterpret_cast<const float4*>(x);
    const float4* t14 = reinterpret_cast<const float4*>(g_T1);
    const float4* p4  = reinterpret_cast<const float4*>(g_P);
    float4* xs4  = reinterpret_cast<float4*>(xs);
    float4* t1s4 = reinterpret_cast<float4*>(t1s);
    float4* t2s4 = reinterpret_cast<float4*>(t2s);

    int tx = tid % 24;
    int ty = tid / 24;

    float4 pf[3 * PFQ];
    int tile = blockIdx.x;
    {
#pragma unroll
        for (int q = 0; q < PFQ; q++) {
            int idx = tid + q * GEMM_THREADS;
            int row = tile * RPB + idx / ROW4;
            float4 xv = make_float4(0.f, 0.f, 0.f, 0.f), t1v = xv, t2v = xv;
            if (row < NN) {
                int gi = row * ROW4 + (idx % ROW4);
                xv = __ldg(x4 + gi);
                t1v = t14[gi];
                float4 pv = p4[gi];
                t2v = make_float4(2.f * pv.x - xv.x, 2.f * pv.y - xv.y,
                                  2.f * pv.z - xv.z, 2.f * pv.w - xv.w);
            }
            pf[q * 3 + 0] = xv; pf[q * 3 + 1] = t1v; pf[q * 3 + 2] = t2v;
        }
    }
    __syncthreads();
#pragma unroll
    for (int q = 0; q < PFQ; q++) {
        int idx = tid + q * GEMM_THREADS;
        xs4[idx] = pf[q * 3 + 0]; t1s4[idx] = pf[q * 3 + 1]; t2s4[idx] = pf[q * 3 + 2];
    }
    __syncthreads();

    float cs[4] = {0.f, 0.f, 0.f, 0.f};
    float cs2[4] = {0.f, 0.f, 0.f, 0.f};

    for (;;) {
        int next = tile + NSM;
        bool has_next = (next < GBLK);

        if (has_next) {
#pragma unroll
            for (int q = 0; q < PFQ; q++) {
                int idx = tid + q * GEMM_THREADS;
                int row = next * RPB + idx / ROW4;
                float4 xv = make_float4(0.f, 0.f, 0.f, 0.f), t1v = xv, t2v = xv;
                if (row < NN) {
                    int gi = row * ROW4 + (idx % ROW4);
                    xv = __ldg(x4 + gi);
                    t1v = t14[gi];
                    float4 pv = p4[gi];
                    t2v = make_float4(2.f * pv.x - xv.x, 2.f * pv.y - xv.y,
                                      2.f * pv.z - xv.z, 2.f * pv.w - xv.w);
                }
                pf[q * 3 + 0] = xv; pf[q * 3 + 1] = t1v; pf[q * 3 + 2] = t2v;
            }
        }

        unsigned long long acc[4][4];
#pragma unroll
        for (int r = 0; r < 4; r++)
#pragma unroll
            for (int jj = 0; jj < 4; jj++) acc[r][jj] = 0ULL;

        const float* xrow  = xs  + ty * 4 * DD;
        const float* t1row = t1s + ty * 4 * DD;
        const float* t2row = t2s + ty * 4 * DD;

        for (int k = 0; k < DD; k += 4) {
            ulonglong2 w0[4], w1[4], w2[4];
#pragma unroll
            for (int jj = 0; jj < 4; jj++) {
                int j = tx + jj * 24;
                w0[jj] = *reinterpret_cast<const ulonglong2*>(&Ws[0 * WS_MAT + j * WS_STRIDE + k]);
                w1[jj] = *reinterpret_cast<const ulonglong2*>(&Ws[1 * WS_MAT + j * WS_STRIDE + k]);
                w2[jj] = *reinterpret_cast<const ulonglong2*>(&Ws[2 * WS_MAT + j * WS_STRIDE + k]);
            }
#pragma unroll
            for (int r = 0; r < 4; r++) {
                ulonglong2 xv = *reinterpret_cast<const ulonglong2*>(&xrow[r * DD + k]);
                ulonglong2 av = *reinterpret_cast<const ulonglong2*>(&t1row[r * DD + k]);
                ulonglong2 bv = *reinterpret_cast<const ulonglong2*>(&t2row[r * DD + k]);
#pragma unroll
                for (int jj = 0; jj < 4; jj++) {
                    ffma2(acc[r][jj], xv.x, w0[jj].x);
                    ffma2(acc[r][jj], xv.y, w0[jj].y);
                    ffma2(acc[r][jj], av.x, w1[jj].x);
                    ffma2(acc[r][jj], av.y, w1[jj].y);
                    ffma2(acc[r][jj], bv.x, w2[jj].x);
                    ffma2(acc[r][jj], bv.y, w2[jj].y);
                }
            }
        }

        int base = tile * RPB;
#pragma unroll
        for (int jj = 0; jj < 4; jj++) {
            int j = tx + jj * 24;
            float bj = bs[j];
#pragma unroll
            for (int r = 0; r < 4; r++) {
                int row = base + ty * 4 + r;
                if (row < NN) {
                    unsigned int lo_b, hi_b;
                    asm("mov.b64 {%0, %1}, %2;" : "=r"(lo_b), "=r"(hi_b) : "l"(acc[r][jj]));
                    float v = __uint_as_float(lo_b) + __uint_as_float(hi_b) + bj;
                    g_acc[row * DD + j] = v;
                    cs[jj] += v; cs2[jj] += v * v;
                }
            }
        }

        if (!has_next) break;
        __syncthreads();
#pragma unroll
        for (int q = 0; q < PFQ; q++) {
            int idx = tid + q * GEMM_THREADS;
            xs4[idx] = pf[q * 3 + 0]; t1s4[idx] = pf[q * 3 + 1]; t2s4[idx] = pf[q * 3 + 2];
        }
        __syncthreads();
        tile = next;
    }

    __syncthreads();
#pragma unroll
    for (int jj = 0; jj < 4; jj++) {
        int j = tx + jj * 24;
        atomicAdd(&stat[j], cs[jj]);
        atomicAdd(&stat[DD + j], cs2[jj]);
    }
    __syncthreads();
    if (tid < DD) {
        atomicAdd(&g_colsum[tid], stat[tid]);
        atomicAdd(&g_colsumsq[tid], stat[DD + tid]);
    }
}

// ---------------- BatchNorm: stats finalize fused into apply ----------------
__global__ void bn_apply_kernel(const float* __restrict__ gamma,
                                const float* __restrict__ beta,
                                float* __restrict__ out) {
    __shared__ float sc[DD], sh[DD];
    if (threadIdx.x < DD) {
        int j = threadIdx.x;
        float inv_n = 1.0f / (float)NN;
        float mean = g_colsum[j] * inv_n;
        float var = fmaxf(g_colsumsq[j] * inv_n - mean * mean, 0.f);
        float istd = rsqrtf(var + 1e-5f);
        float s = gamma[j] * istd;
        sc[j] = s;
        sh[j] = beta[j] - mean * s;
    }
    __syncthreads();
    int tid = blockIdx.x * blockDim.x + threadIdx.x;
    int stride = gridDim.x * blockDim.x;
    const float4* in4 = reinterpret_cast<const float4*>(g_acc);
    float4* o4 = reinterpret_cast<float4*>(out);
    for (int i = tid; i < NV4; i += stride) {
        int c4 = i % (DD / 4);
        int j = c4 * 4;
        float4 v = in4[i];
        o4[i] = make_float4(v.x * sc[j]     + sh[j],
                            v.y * sc[j + 1] + sh[j + 1],
                            v.z * sc[j + 2] + sh[j + 2],
                            v.w * sc[j + 3] + sh[j + 3]);
    }
}

// ---------------- launch ----------------------------------------------------
extern "C" void kernel_launch(void* const* d_in, const int* in_sizes, int n_in,
                              void* d_out, int out_size) {
    const float* x     = (const float*)d_in[0];
    const int*   ei    = (const int*)d_in[1];
    const float* W     = (const float*)d_in[2];
    const float* bias  = (const float*)d_in[3];
    const float* gamma = (const float*)d_in[4];
    const float* beta  = (const float*)d_in[5];
    float* out = (float*)d_out;

    cudaFuncSetAttribute(gemm_kernel,
                         cudaFuncAttributeMaxDynamicSharedMemorySize, SMEM_BYTES);

    zero_kernel<<<256, 256>>>();
    hist_kernel<<<(EE / 4 + 255) / 256, 256>>>(ei);
    scan1_kernel<<<NBLK, 256>>>();
    scan2_kernel<<<NBLK, 256>>>();     // merged scan2+scan3
    scatter_kernel<<<(EE / 4 + 255) / 256, 256>>>(ei);
    // prop 1: T1 = L_hat @ x  (pull, no atomics, no zero-init)
    spmm_pull_kernel<<<(NN * 32 + 255) / 256, 256>>>(0, x);
    // prop 2: P = L_hat @ T1
    spmm_pull_kernel<<<(NN * 32 + 255) / 256, 256>>>(1, x);
    gemm_kernel<<<NSM, GEMM_THREADS, SMEM_BYTES>>>(x, W, bias);
    bn_apply_kernel<<<2048, 256>>>(gamma, beta, out);
}

// round 16
// speedup vs baseline: 1.0261x; 1.0154x over previous
#include <cuda_runtime.h>

#define NN 50000
#define EE 800000
#define DD 96
#define NV4 (NN * DD / 4)
#define NBLK ((NN + 255) / 256)        // 196 scan blocks

// ---------------- scratch (device globals; no allocation allowed) ----------
__device__ __align__(256) float g_deg[NN];      // out-degree (by row)
__device__ __align__(256) int   g_cnt[NN];      // in-degree (by col)
__device__ __align__(256) int   g_ptr[NN + 1];  // CSR row pointers (by dst)
__device__ __align__(256) int   g_fill[NN];     // atomic cursors
__device__ __align__(256) int   g_bsum[256];    // scan block sums
__device__ __align__(256) int2  g_cedge[EE];    // {src_row, norm bits}
__device__ __align__(256) float g_T1[NN * DD];
__device__ __align__(256) float g_P[NN * DD];
__device__ __align__(256) float g_acc[NN * DD];
__device__ __align__(256) float g_colsum[DD];
__device__ __align__(256) float g_colsumsq[DD];

// ---------------- packed f32x2 FMA (SASS FFMA2) -----------------------------
__device__ __forceinline__ void ffma2(unsigned long long& d,
                                      unsigned long long a,
                                      unsigned long long b) {
    asm("fma.rn.f32x2 %0, %1, %2, %0;" : "+l"(d) : "l"(a), "l"(b));
}

// ---------------- histogram (round-13 scalar) + colsum zero fold ------------
// deg/cnt are zeroed by the PREVIOUS replay's spmm pass 0 (and are
// statically zero-initialized on the very first call).
__global__ void hist_kernel(const int* __restrict__ ei) {
    if (blockIdx.x == 0 && threadIdx.x < DD) {
        g_colsum[threadIdx.x] = 0.f;
        g_colsumsq[threadIdx.x] = 0.f;
    }
    int e = blockIdx.x * blockDim.x + threadIdx.x;
    if (e >= EE) return;
    int r = ei[e], c = ei[EE + e];
    if (r != c) {
        atomicAdd(&g_deg[r], 1.0f);
        atomicAdd(&g_cnt[c], 1);
    }
}

// ---------------- scan stage 1: per-block scan + block sums -----------------
__global__ void scan1_kernel() {
    __shared__ int sh[256];
    int i = blockIdx.x * 256 + threadIdx.x;
    int v = (i < NN) ? g_cnt[i] : 0;
    sh[threadIdx.x] = v;
    __syncthreads();
#pragma unroll
    for (int off = 1; off < 256; off <<= 1) {
        int t = (threadIdx.x >= off) ? sh[threadIdx.x - off] : 0;
        __syncthreads();
        sh[threadIdx.x] += t;
        __syncthreads();
    }
    if (i < NN) g_ptr[i] = sh[threadIdx.x] - v;  // block-local exclusive
    if (threadIdx.x == 255) g_bsum[blockIdx.x] = sh[255];
}

// ---------------- scan stage 2 (merged): redundant sum-scan + apply ---------
__global__ void scan2_kernel() {
    __shared__ int sh[256];
    __shared__ int myoff;
    int b = threadIdx.x;
    int v = (b < NBLK) ? g_bsum[b] : 0;
    sh[b] = v;
    __syncthreads();
#pragma unroll
    for (int off = 1; off < 256; off <<= 1) {
        int t = (b >= off) ? sh[b - off] : 0;
        __syncthreads();
        sh[b] += t;
        __syncthreads();
    }
    if (threadIdx.x == blockIdx.x) myoff = sh[threadIdx.x] - v;
    __syncthreads();
    int i = blockIdx.x * 256 + threadIdx.x;
    if (i < NN) {
        int p = g_ptr[i] + myoff;
        g_ptr[i] = p;
        g_fill[i] = p;
    }
    if (blockIdx.x == NBLK - 1 && threadIdx.x == 255)
        g_ptr[NN] = sh[NBLK - 1];
}

// ---------------- scatter (round-13 scalar, norm inline) --------------------
__global__ void scatter_kernel(const int* __restrict__ ei) {
    int e = blockIdx.x * blockDim.x + threadIdx.x;
    if (e >= EE) return;
    int r = ei[e], c = ei[EE + e];
    if (r == c) return;
    float dr = g_deg[r], dc = g_deg[c];
    float ir = (dr > 0.f) ? rsqrtf(fmaxf(dr, 1e-12f)) : 0.f;
    float ic = (dc > 0.f) ? rsqrtf(fmaxf(dc, 1e-12f)) : 0.f;
    float nrm = -ir * ic;
    int pos = atomicAdd(&g_fill[c], 1);
    g_cedge[pos] = make_int2(r, __float_as_int(nrm));
}

// ---------------- pull-mode SpMM (round-13) + deg/cnt zero fold -------------
// Pass 0 also zeroes g_deg/g_cnt for the NEXT replay: scatter (last g_deg
// reader) and scan1 (last g_cnt reader) have already completed this replay.
__global__ void spmm_pull_kernel(int pass, const float* __restrict__ x) {
    if (pass == 0) {
        int zi = blockIdx.x * 256 + threadIdx.x;
        if (zi < NN) { g_deg[zi] = 0.f; g_cnt[zi] = 0; }
    }

    const float* src = (pass == 0) ? x : g_T1;
    float* dst = (pass == 0) ? g_T1 : g_P;

    int node = (blockIdx.x * blockDim.x + threadIdx.x) >> 5;
    if (node >= NN) return;
    int lane = threadIdx.x & 31;

    int beg = g_ptr[node], end = g_ptr[node + 1];
    float a0 = 0.f, a1 = 0.f, a2 = 0.f;

    int e = beg;
    for (; e + 1 < end; e += 2) {
        int2 e0 = __ldg(&g_cedge[e]);
        int2 e1 = __ldg(&g_cedge[e + 1]);
        float n0 = __int_as_float(e0.y);
        float n1 = __int_as_float(e1.y);
        const float* s0 = src + e0.x * DD;
        const float* s1 = src + e1.x * DD;
        float v00 = __ldg(s0 + lane), v01 = __ldg(s0 + lane + 32), v02 = __ldg(s0 + lane + 64);
        float v10 = __ldg(s1 + lane), v11 = __ldg(s1 + lane + 32), v12 = __ldg(s1 + lane + 64);
        a0 += n0 * v00 + n1 * v10;
        a1 += n0 * v01 + n1 * v11;
        a2 += n0 * v02 + n1 * v12;
    }
    if (e < end) {
        int2 e0 = __ldg(&g_cedge[e]);
        float n0 = __int_as_float(e0.y);
        const float* s0 = src + e0.x * DD;
        a0 += n0 * __ldg(s0 + lane);
        a1 += n0 * __ldg(s0 + lane + 32);
        a2 += n0 * __ldg(s0 + lane + 64);
    }

    float* d = dst + node * DD;
    d[lane] = a0;
    d[lane + 32] = a1;
    d[lane + 64] = a2;
}

// ---------------- persistent GEMM: conflict-free warp-tiled layout ----------
// tx = (wid%3)*8 + lane%8 (24 j-positions), ty = (wid/3)*4 + lane/8 (16).
// Thread rows = ty + 16r. Row smem stride 100 floats -> every LDS.128
// (w and rows) is single-phase. Warp w-footprint 8 tx instead of 24.
#define GEMM_THREADS 384
#define RPB 64
#define NSM 148
#define WS_STRIDE 100
#define RS 100                               // row smem stride (floats)
#define RS4 25                               // float4 stride
#define WS_MAT (DD * WS_STRIDE)
#define GBLK ((NN + RPB - 1) / RPB)
#define ROW4 (DD / 4)
#define TILE4 (RPB * ROW4)                   // 1536
#define PFQ (TILE4 / GEMM_THREADS)           // 4
#define SMEM_FLOATS (3 * WS_MAT + DD + 3 * RPB * RS + 2 * DD)
#define SMEM_BYTES (SMEM_FLOATS * 4)         // 193,152 B

__global__ __launch_bounds__(GEMM_THREADS, 1)
void gemm_kernel(const float* __restrict__ x, const float* __restrict__ W,
                 const float* __restrict__ bias) {
    extern __shared__ float smem[];
    float* Ws   = smem;                      // [3][96*100]
    float* bs   = Ws + 3 * WS_MAT;           // [96]
    float* xs   = bs + DD;                   // [64 rows x 100]
    float* t1s  = xs + RPB * RS;
    float* t2s  = t1s + RPB * RS;
    float* stat = t2s + RPB * RS;            // [2][96]

    int tid = threadIdx.x;
    int wid = tid >> 5, lane = tid & 31;
    int tx = (wid % 3) * 8 + (lane & 7);     // 0..23
    int ty = (wid / 3) * 4 + (lane >> 3);    // 0..15

    for (int i = tid; i < 3 * DD * DD; i += GEMM_THREADS) {
        int kk = i / (DD * DD);
        int rem = i - kk * DD * DD;
        int k = rem / DD;
        int j = rem - k * DD;
        Ws[kk * WS_MAT + j * WS_STRIDE + k] = W[i];
    }
    if (tid < DD) bs[tid] = bias[tid];
    if (tid < 2 * DD) stat[tid] = 0.f;

    const float4* x4  = reinterpret_cast<const float4*>(x);
    const float4* t14 = reinterpret_cast<const float4*>(g_T1);
    const float4* p4  = reinterpret_cast<const float4*>(g_P);
    float4* xs4  = reinterpret_cast<float4*>(xs);
    float4* t1s4 = reinterpret_cast<float4*>(t1s);
    float4* t2s4 = reinterpret_cast<float4*>(t2s);

    float4 pf[3 * PFQ];
    int tile = blockIdx.x;
    {
#pragma unroll
        for (int q = 0; q < PFQ; q++) {
            int idx = tid + q * GEMM_THREADS;
            int row = tile * RPB + idx / ROW4;
            float4 xv = make_float4(0.f, 0.f, 0.f, 0.f), t1v = xv, t2v = xv;
            if (row < NN) {
                int gi = row * ROW4 + (idx % ROW4);
                xv = __ldg(x4 + gi);
                t1v = t14[gi];
                float4 pv = p4[gi];
                t2v = make_float4(2.f * pv.x - xv.x, 2.f * pv.y - xv.y,
                                  2.f * pv.z - xv.z, 2.f * pv.w - xv.w);
            }
            pf[q * 3 + 0] = xv; pf[q * 3 + 1] = t1v; pf[q * 3 + 2] = t2v;
        }
    }
    __syncthreads();
#pragma unroll
    for (int q = 0; q < PFQ; q++) {
        int idx = tid + q * GEMM_THREADS;
        int si = (idx / ROW4) * RS4 + (idx % ROW4);   // padded row stride
        xs4[si] = pf[q * 3 + 0]; t1s4[si] = pf[q * 3 + 1]; t2s4[si] = pf[q * 3 + 2];
    }
    __syncthreads();

    float cs[4] = {0.f, 0.f, 0.f, 0.f};
    float cs2[4] = {0.f, 0.f, 0.f, 0.f};

    for (;;) {
        int next = tile + NSM;
        bool has_next = (next < GBLK);

        if (has_next) {
#pragma unroll
            for (int q = 0; q < PFQ; q++) {
                int idx = tid + q * GEMM_THREADS;
                int row = next * RPB + idx / ROW4;
                float4 xv = make_float4(0.f, 0.f, 0.f, 0.f), t1v = xv, t2v = xv;
                if (row < NN) {
                    int gi = row * ROW4 + (idx % ROW4);
                    xv = __ldg(x4 + gi);
                    t1v = t14[gi];
                    float4 pv = p4[gi];
                    t2v = make_float4(2.f * pv.x - xv.x, 2.f * pv.y - xv.y,
                                      2.f * pv.z - xv.z, 2.f * pv.w - xv.w);
                }
                pf[q * 3 + 0] = xv; pf[q * 3 + 1] = t1v; pf[q * 3 + 2] = t2v;
            }
        }

        unsigned long long acc[4][4];
#pragma unroll
        for (int r = 0; r < 4; r++)
#pragma unroll
            for (int jj = 0; jj < 4; jj++) acc[r][jj] = 0ULL;

        for (int k = 0; k < DD; k += 4) {
            ulonglong2 w0[4], w1[4], w2[4];
#pragma unroll
            for (int jj = 0; jj < 4; jj++) {
                int j = tx + jj * 24;
                w0[jj] = *reinterpret_cast<const ulonglong2*>(&Ws[0 * WS_MAT + j * WS_STRIDE + k]);
                w1[jj] = *reinterpret_cast<const ulonglong2*>(&Ws[1 * WS_MAT + j * WS_STRIDE + k]);
                w2[jj] = *reinterpret_cast<const ulonglong2*>(&Ws[2 * WS_MAT + j * WS_STRIDE + k]);
            }
#pragma unroll
            for (int r = 0; r < 4; r++) {
                int rofs = (ty + 16 * r) * RS + k;
                ulonglong2 xv = *reinterpret_cast<const ulonglong2*>(&xs[rofs]);
                ulonglong2 av = *reinterpret_cast<const ulonglong2*>(&t1s[rofs]);
                ulonglong2 bv = *reinterpret_cast<const ulonglong2*>(&t2s[rofs]);
#pragma unroll
                for (int jj = 0; jj < 4; jj++) {
                    ffma2(acc[r][jj], xv.x, w0[jj].x);
                    ffma2(acc[r][jj], xv.y, w0[jj].y);
                    ffma2(acc[r][jj], av.x, w1[jj].x);
                    ffma2(acc[r][jj], av.y, w1[jj].y);
                    ffma2(acc[r][jj], bv.x, w2[jj].x);
                    ffma2(acc[r][jj], bv.y, w2[jj].y);
                }
            }
        }

        int base = tile * RPB;
#pragma unroll
        for (int jj = 0; jj < 4; jj++) {
            int j = tx + jj * 24;
            float bj = bs[j];
#pragma unroll
            for (int r = 0; r < 4; r++) {
                int row = base + ty + 16 * r;
                if (row < NN) {
                    unsigned int lo_b, hi_b;
                    asm("mov.b64 {%0, %1}, %2;" : "=r"(lo_b), "=r"(hi_b) : "l"(acc[r][jj]));
                    float v = __uint_as_float(lo_b) + __uint_as_float(hi_b) + bj;
                    g_acc[row * DD + j] = v;
                    cs[jj] += v; cs2[jj] += v * v;
                }
            }
        }

        if (!has_next) break;
        __syncthreads();
#pragma unroll
        for (int q = 0; q < PFQ; q++) {
            int idx = tid + q * GEMM_THREADS;
            int si = (idx / ROW4) * RS4 + (idx % ROW4);
            xs4[si] = pf[q * 3 + 0]; t1s4[si] = pf[q * 3 + 1]; t2s4[si] = pf[q * 3 + 2];
        }
        __syncthreads();
        tile = next;
    }

    // per-block stats reduction -> 2 global atomics per column
    __syncthreads();
#pragma unroll
    for (int jj = 0; jj < 4; jj++) {
        int j = tx + jj * 24;
        atomicAdd(&stat[j], cs[jj]);
        atomicAdd(&stat[DD + j], cs2[jj]);
    }
    __syncthreads();
    if (tid < DD) {
        atomicAdd(&g_colsum[tid], stat[tid]);
        atomicAdd(&g_colsumsq[tid], stat[DD + tid]);
    }
}

// ---------------- BatchNorm: stats finalize fused into apply ----------------
__global__ void bn_apply_kernel(const float* __restrict__ gamma,
                                const float* __restrict__ beta,
                                float* __restrict__ out) {
    __shared__ float sc[DD], sh[DD];
    if (threadIdx.x < DD) {
        int j = threadIdx.x;
        float inv_n = 1.0f / (float)NN;
        float mean = g_colsum[j] * inv_n;
        float var = fmaxf(g_colsumsq[j] * inv_n - mean * mean, 0.f);
        float istd = rsqrtf(var + 1e-5f);
        float s = gamma[j] * istd;
        sc[j] = s;
        sh[j] = beta[j] - mean * s;
    }
    __syncthreads();
    int tid = blockIdx.x * blockDim.x + threadIdx.x;
    int stride = gridDim.x * blockDim.x;
    const float4* in4 = reinterpret_cast<const float4*>(g_acc);
    float4* o4 = reinterpret_cast<float4*>(out);
    for (int i = tid; i < NV4; i += stride) {
        int c4 = i % (DD / 4);
        int j = c4 * 4;
        float4 v = in4[i];
        o4[i] = make_float4(v.x * sc[j]     + sh[j],
                            v.y * sc[j + 1] + sh[j + 1],
                            v.z * sc[j + 2] + sh[j + 2],
                            v.w * sc[j + 3] + sh[j + 3]);
    }
}

// ---------------- launch ----------------------------------------------------
extern "C" void kernel_launch(void* const* d_in, const int* in_sizes, int n_in,
                              void* d_out, int out_size) {
    const float* x     = (const float*)d_in[0];
    const int*   ei    = (const int*)d_in[1];
    const float* W     = (const float*)d_in[2];
    const float* bias  = (const float*)d_in[3];
    const float* gamma = (const float*)d_in[4];
    const float* beta  = (const float*)d_in[5];
    float* out = (float*)d_out;

    cudaFuncSetAttribute(gemm_kernel,
                         cudaFuncAttributeMaxDynamicSharedMemorySize, SMEM_BYTES);

    hist_kernel<<<(EE + 255) / 256, 256>>>(ei);       // + colsum zero
    scan1_kernel<<<NBLK, 256>>>();
    scan2_kernel<<<NBLK, 256>>>();                    // merged scan+apply
    scatter_kernel<<<(EE + 255) / 256, 256>>>(ei);
    // prop 1: T1 = L_hat @ x  (+ deg/cnt zero for next replay)
    spmm_pull_kernel<<<(NN * 32 + 255) / 256, 256>>>(0, x);
    // prop 2: P = L_hat @ T1
    spmm_pull_kernel<<<(NN * 32 + 255) / 256, 256>>>(1, x);
    gemm_kernel<<<NSM, GEMM_THREADS, SMEM_BYTES>>>(x, W, bias);
    bn_apply_kernel<<<2048, 256>>>(gamma, beta, out);
}